// round 1
// baseline (speedup 1.0000x reference)
#include <cuda_runtime.h>
#include <cstddef>

#define N_ROWS 65536
#define HID    1024
#define D_IN   512

// Scratch activations (ping-pong). __device__ globals are the sanctioned
// scratch mechanism (no allocations allowed anywhere).
__device__ float g_bufA[(size_t)N_ROWS * HID];
__device__ float g_bufB[(size_t)N_ROWS * HID];

// ---------------------------------------------------------------------------
// Tiled fp32 GEMM: C[M,N] = A[M,K] @ B[K,N], optional fused bias+ReLU.
// BM=BN=128, BK=16, 256 threads, 8x8 register tile per thread.
// M=65536, N=1024, K in {512,1024} -> all tiles exact, no bounds checks.
// ---------------------------------------------------------------------------
template<int K, bool BIAS_RELU>
__global__ __launch_bounds__(256)
void gemm128(const float* __restrict__ A, const float* __restrict__ B,
             const float* __restrict__ bias, float* __restrict__ C, int N)
{
    __shared__ float As[16][132];   // padded: conflict-free transposed stores
    __shared__ float Bs[16][128];

    const int tid = threadIdx.x;
    const int tx  = tid & 15;       // 16 thread cols
    const int ty  = tid >> 4;       // 16 thread rows
    const int m0  = blockIdx.y * 128;
    const int n0  = blockIdx.x * 128;

    const float* Aptr = A + (size_t)m0 * K;
    const float* Bptr = B + n0;

    float acc[8][8];
#pragma unroll
    for (int i = 0; i < 8; i++)
#pragma unroll
        for (int j = 0; j < 8; j++) acc[i][j] = 0.f;

    for (int k0 = 0; k0 < K; k0 += 16) {
        // A tile: 128 rows x 16 cols, stored transposed As[k][m]
#pragma unroll
        for (int i = 0; i < 2; i++) {
            int idx = tid + i * 256;        // 512 float4s total
            int r   = idx >> 2;             // row 0..127
            int c4  = idx & 3;              // which float4 in the 16-wide row
            float4 v = *(const float4*)(Aptr + (size_t)r * K + k0 + c4 * 4);
            As[c4 * 4 + 0][r] = v.x;
            As[c4 * 4 + 1][r] = v.y;
            As[c4 * 4 + 2][r] = v.z;
            As[c4 * 4 + 3][r] = v.w;
        }
        // B tile: 16 rows x 128 cols, row-major
#pragma unroll
        for (int i = 0; i < 2; i++) {
            int idx = tid + i * 256;        // 512 float4s total
            int r   = idx >> 5;             // row 0..15
            int c4  = idx & 31;             // 32 float4s per row
            float4 v = *(const float4*)(Bptr + (size_t)(k0 + r) * N + c4 * 4);
            *(float4*)(&Bs[r][c4 * 4]) = v;
        }
        __syncthreads();

#pragma unroll
        for (int k = 0; k < 16; k++) {
            float am[8], bn[8];
#pragma unroll
            for (int i = 0; i < 8; i++) am[i] = As[k][ty * 8 + i];
#pragma unroll
            for (int j = 0; j < 8; j++) bn[j] = Bs[k][tx * 8 + j];
#pragma unroll
            for (int i = 0; i < 8; i++)
#pragma unroll
                for (int j = 0; j < 8; j++)
                    acc[i][j] = fmaf(am[i], bn[j], acc[i][j]);
        }
        __syncthreads();
    }

    // Epilogue
#pragma unroll
    for (int i = 0; i < 8; i++) {
        const int m = m0 + ty * 8 + i;
        float* Crow = C + (size_t)m * N + n0 + tx * 8;
#pragma unroll
        for (int jj = 0; jj < 2; jj++) {
            float4 v;
            float* a4 = &acc[i][jj * 4];
            v.x = a4[0]; v.y = a4[1]; v.z = a4[2]; v.w = a4[3];
            if (BIAS_RELU) {
                const float* bp = bias + n0 + tx * 8 + jj * 4;
                v.x = fmaxf(v.x + bp[0], 0.f);
                v.y = fmaxf(v.y + bp[1], 0.f);
                v.z = fmaxf(v.z + bp[2], 0.f);
                v.w = fmaxf(v.w + bp[3], 0.f);
            }
            *(float4*)(Crow + jj * 4) = v;
        }
    }
}

// ---------------------------------------------------------------------------
// Row LayerNorm(+scale,+bias) + ReLU in place. One block (256 thr) per row of
// 1024 floats; each thread owns one float4.
// ---------------------------------------------------------------------------
__global__ __launch_bounds__(256)
void ln_relu(float* __restrict__ H, const float* __restrict__ g,
             const float* __restrict__ be)
{
    const int row = blockIdx.x;
    const int tid = threadIdx.x;
    float4* p = (float4*)(H + (size_t)row * 1024);

    float4 v = p[tid];
    float s  = v.x + v.y + v.z + v.w;
    float sq = v.x * v.x + v.y * v.y + v.z * v.z + v.w * v.w;

    __shared__ float ss[8], ssq[8];
    const int lane = tid & 31, warp = tid >> 5;
#pragma unroll
    for (int o = 16; o > 0; o >>= 1) {
        s  += __shfl_down_sync(0xffffffffu, s,  o);
        sq += __shfl_down_sync(0xffffffffu, sq, o);
    }
    if (lane == 0) { ss[warp] = s; ssq[warp] = sq; }
    __syncthreads();
    if (warp == 0) {
        s  = (lane < 8) ? ss[lane]  : 0.f;
        sq = (lane < 8) ? ssq[lane] : 0.f;
#pragma unroll
        for (int o = 4; o > 0; o >>= 1) {
            s  += __shfl_down_sync(0xffffffffu, s,  o);
            sq += __shfl_down_sync(0xffffffffu, sq, o);
        }
        if (lane == 0) { ss[0] = s; ssq[0] = sq; }
    }
    __syncthreads();

    const float mean = ss[0] * (1.0f / 1024.0f);
    const float var  = ssq[0] * (1.0f / 1024.0f) - mean * mean;
    const float rstd = rsqrtf(var + 1e-6f);

    float4 gv = ((const float4*)g)[tid];
    float4 bv = ((const float4*)be)[tid];
    float4 o;
    o.x = fmaxf(fmaf((v.x - mean) * rstd, gv.x, bv.x), 0.f);
    o.y = fmaxf(fmaf((v.y - mean) * rstd, gv.y, bv.y), 0.f);
    o.z = fmaxf(fmaf((v.z - mean) * rstd, gv.z, bv.z), 0.f);
    o.w = fmaxf(fmaf((v.w - mean) * rstd, gv.w, bv.w), 0.f);
    p[tid] = o;
}

// ---------------------------------------------------------------------------
// Output layer: out[row] = relu(dot(H[row,:], Wout) + bout). Warp per row.
// ---------------------------------------------------------------------------
__global__ __launch_bounds__(256)
void out_layer(const float* __restrict__ H, const float* __restrict__ Wout,
               const float* __restrict__ bout, float* __restrict__ out)
{
    const int row  = blockIdx.x * 8 + (threadIdx.x >> 5);
    const int lane = threadIdx.x & 31;
    const float* p = H + (size_t)row * 1024;

    float s = 0.f;
#pragma unroll
    for (int t = 0; t < 32; t++) {
        const int j = t * 32 + lane;
        s = fmaf(p[j], __ldg(Wout + j), s);
    }
#pragma unroll
    for (int o = 16; o > 0; o >>= 1) s += __shfl_down_sync(0xffffffffu, s, o);
    if (lane == 0) out[row] = fmaxf(s + bout[0], 0.f);
}

// ---------------------------------------------------------------------------
extern "C" void kernel_launch(void* const* d_in, const int* in_sizes, int n_in,
                              void* d_out, int out_size)
{
    const float* X    = (const float*)d_in[0];
    const float* W0   = (const float*)d_in[1];
    const float* b0   = (const float*)d_in[2];
    const float* W1   = (const float*)d_in[3];
    const float* g1   = (const float*)d_in[4];
    const float* be1  = (const float*)d_in[5];
    const float* W2   = (const float*)d_in[6];
    const float* g2   = (const float*)d_in[7];
    const float* be2  = (const float*)d_in[8];
    const float* W3   = (const float*)d_in[9];
    const float* g3   = (const float*)d_in[10];
    const float* be3  = (const float*)d_in[11];
    const float* Wout = (const float*)d_in[12];
    const float* bout = (const float*)d_in[13];
    float* out = (float*)d_out;

    float *bufA, *bufB;
    cudaGetSymbolAddress((void**)&bufA, g_bufA);
    cudaGetSymbolAddress((void**)&bufB, g_bufB);

    dim3 grid(HID / 128, N_ROWS / 128);   // (8, 512)

    // layer 0: Dense + bias + relu
    gemm128<D_IN, true><<<grid, 256>>>(X, W0, b0, bufA, HID);

    // hidden layers: Dense -> LN -> relu
    gemm128<HID, false><<<grid, 256>>>(bufA, W1, nullptr, bufB, HID);
    ln_relu<<<N_ROWS, 256>>>(bufB, g1, be1);

    gemm128<HID, false><<<grid, 256>>>(bufB, W2, nullptr, bufA, HID);
    ln_relu<<<N_ROWS, 256>>>(bufA, g2, be2);

    gemm128<HID, false><<<grid, 256>>>(bufA, W3, nullptr, bufB, HID);
    ln_relu<<<N_ROWS, 256>>>(bufB, g3, be3);

    // output layer
    out_layer<<<N_ROWS / 8, 256>>>(bufB, Wout, bout, out);
}

// round 3
// speedup vs baseline: 4.0107x; 4.0107x over previous
#include <cuda_runtime.h>
#include <cstdint>
#include <cstddef>

#define N_ROWS 65536
#define HID    1024
#define D_IN   512

// ---------------- scratch (__device__ globals: the sanctioned mechanism) ----
__device__ float g_bufA[(size_t)N_ROWS * HID];
__device__ float g_bufB[(size_t)N_ROWS * HID];
__device__ float g_wt0[HID * D_IN];      // W0^T  [1024][512]
__device__ float g_wt1[HID * HID];
__device__ float g_wt2[HID * HID];
__device__ float g_wt3[HID * HID];

// ---------------- helpers ---------------------------------------------------
__device__ __forceinline__ uint32_t smem_u32(const void* p) {
    uint32_t a;
    asm("{ .reg .u64 t; cvta.to.shared.u64 t, %1; cvt.u32.u64 %0, t; }"
        : "=r"(a) : "l"(p));
    return a;
}
__device__ __forceinline__ float rna_tf32(float x) {
    uint32_t b;
    asm("cvt.rna.tf32.f32 %0, %1;" : "=r"(b) : "f"(x));
    return __uint_as_float(b);
}
__device__ __forceinline__ void ldsm_x4(uint32_t* d, uint32_t addr) {
    asm volatile("ldmatrix.sync.aligned.m8n8.x4.shared.b16 {%0,%1,%2,%3}, [%4];"
                 : "=r"(d[0]), "=r"(d[1]), "=r"(d[2]), "=r"(d[3]) : "r"(addr));
}
__device__ __forceinline__ void mma_tf32(float* c, const uint32_t* a,
                                         uint32_t b0, uint32_t b1) {
    asm volatile(
        "mma.sync.aligned.m16n8k8.row.col.f32.tf32.tf32.f32 "
        "{%0,%1,%2,%3}, {%4,%5,%6,%7}, {%8,%9}, {%0,%1,%2,%3};"
        : "+f"(c[0]), "+f"(c[1]), "+f"(c[2]), "+f"(c[3])
        : "r"(a[0]), "r"(a[1]), "r"(a[2]), "r"(a[3]), "r"(b0), "r"(b1));
}
__device__ __forceinline__ void cp16(uint32_t dst, const void* src) {
    asm volatile("cp.async.cg.shared.global [%0], [%1], 16;" :: "r"(dst), "l"(src));
}

// ---------------------------------------------------------------------------
// tf32 mma.sync GEMM: C[M,1024] = A[M,K] @ Bt[1024,K]^T   (+ optional epi)
// BM=128, BN=128, BK=32, 3-stage cp.async pipeline, 256 threads (8 warps),
// warp tile 64x32 (m16n8k8 frags). XOR-swizzled smem (16B chunks, 128B rows).
// grid = (8, M/128). EPI=1: out = rna(relu(acc + bias)); EPI=0: raw store.
// ---------------------------------------------------------------------------
template<int K, int EPI>
__global__ __launch_bounds__(256, 2)
void gemm_mma(const float* __restrict__ A, const float* __restrict__ Bt,
              const float* __restrict__ bias, float* __restrict__ C)
{
    constexpr int KT = K / 32;                 // k-tiles
    constexpr int STAGE_BYTES = 32768;         // A 16K + B 16K

    extern __shared__ char smem[];
    const uint32_t sb = smem_u32(smem);

    const int tid  = threadIdx.x;
    const int lane = tid & 31, warp = tid >> 5;
    const int wm   = warp & 1;                  // 2 warps in m
    const int wn   = warp >> 1;                 // 4 warps in n
    const int m0   = blockIdx.y * 128;
    const int n0   = blockIdx.x * 128;

    // ---- cp.async source/dest layout ----
    // 1024 16B-chunks per tile per matrix; thread does 4 (row = tid>>3 + 32i,
    // chunk col c = tid&7). Swizzle: phys_chunk = c ^ (row & 7).
    const int ldr = tid >> 3;                   // 0..31
    const int ldc = tid & 7;
    const uint32_t swz16 = (uint32_t)((ldc ^ (ldr & 7)) * 16);
    const float* Ag = A  + (size_t)(m0 + ldr) * K + ldc * 4;
    const float* Bg = Bt + (size_t)(n0 + ldr) * K + ldc * 4;

    auto load_tile = [&](int kt) {
        const uint32_t st = sb + (uint32_t)(kt % 3) * STAGE_BYTES;
        const float* ag = Ag + kt * 32;
        const float* bg = Bg + kt * 32;
#pragma unroll
        for (int i = 0; i < 4; i++) {
            const uint32_t off = (uint32_t)((ldr + i * 32) * 128) + swz16;
            cp16(st + off,         ag + (size_t)i * 32 * K);
            cp16(st + 16384 + off, bg + (size_t)i * 32 * K);
        }
        asm volatile("cp.async.commit_group;" ::: "memory");
    };

    // ---- ldmatrix per-thread geometry ----
    const uint32_t xm   = (uint32_t)(lane & 7);          // swizzle xor
    const uint32_t Arow = (uint32_t)(wm * 64 + (lane & 15));
    const uint32_t hiA  = (uint32_t)(lane >> 4);
    const uint32_t Brow = (uint32_t)(wn * 32 + (lane & 7) + ((lane >> 4) << 3));
    const uint32_t hiB  = (uint32_t)((lane >> 3) & 1);

    float acc[4][4][4];
#pragma unroll
    for (int i = 0; i < 4; i++)
#pragma unroll
        for (int j = 0; j < 4; j++)
#pragma unroll
            for (int q = 0; q < 4; q++) acc[i][j][q] = 0.f;

    load_tile(0);
    load_tile(1);

    for (int kt = 0; kt < KT; kt++) {
        if (kt + 1 < KT) asm volatile("cp.async.wait_group 1;" ::: "memory");
        else             asm volatile("cp.async.wait_group 0;" ::: "memory");
        __syncthreads();
        if (kt + 2 < KT) load_tile(kt + 2);

        const uint32_t st    = sb + (uint32_t)(kt % 3) * STAGE_BYTES;
        const uint32_t abase = st + Arow * 128;
        const uint32_t bbase = st + 16384 + Brow * 128;

#pragma unroll
        for (int ks = 0; ks < 4; ks++) {
            uint32_t a[4][4];
            const uint32_t qa = ((2u * ks + hiA) ^ xm) * 16u;
#pragma unroll
            for (int mi = 0; mi < 4; mi++)
                ldsm_x4(a[mi], abase + (uint32_t)mi * 2048 + qa);

            uint32_t b[2][4];                   // [np]{b0,b1 of ni, b0,b1 of ni+1}
            const uint32_t qb = ((2u * ks + hiB) ^ xm) * 16u;
#pragma unroll
            for (int np = 0; np < 2; np++)
                ldsm_x4(b[np], bbase + (uint32_t)np * 2048 + qb);

#pragma unroll
            for (int mi = 0; mi < 4; mi++)
#pragma unroll
                for (int ni = 0; ni < 4; ni++)
                    mma_tf32(acc[mi][ni], a[mi],
                             b[ni >> 1][(ni & 1) * 2], b[ni >> 1][(ni & 1) * 2 + 1]);
        }
    }

    // ---- epilogue ----
#pragma unroll
    for (int mi = 0; mi < 4; mi++) {
        const int r = m0 + wm * 64 + mi * 16 + (lane >> 2);
#pragma unroll
        for (int ni = 0; ni < 4; ni++) {
            const int col = n0 + wn * 32 + ni * 8 + (lane & 3) * 2;
            float c0 = acc[mi][ni][0], c1 = acc[mi][ni][1];
            float c2 = acc[mi][ni][2], c3 = acc[mi][ni][3];
            if (EPI) {
                const float b0v = bias[col], b1v = bias[col + 1];
                c0 = rna_tf32(fmaxf(c0 + b0v, 0.f));
                c1 = rna_tf32(fmaxf(c1 + b1v, 0.f));
                c2 = rna_tf32(fmaxf(c2 + b0v, 0.f));
                c3 = rna_tf32(fmaxf(c3 + b1v, 0.f));
            }
            float2* p0 = (float2*)(C + (size_t)r * HID + col);
            float2* p1 = (float2*)(C + (size_t)(r + 8) * HID + col);
            *p0 = make_float2(c0, c1);
            *p1 = make_float2(c2, c3);
        }
    }
}

// ---------------------------------------------------------------------------
// Round-copy: out[i] = rna_tf32(in[i])  (for raw input X)
// ---------------------------------------------------------------------------
__global__ __launch_bounds__(256)
void round_copy(const float* __restrict__ in, float* __restrict__ out)
{
    const size_t i = ((size_t)blockIdx.x * 256 + threadIdx.x) * 4;
    float4 v = *(const float4*)(in + i);
    v.x = rna_tf32(v.x); v.y = rna_tf32(v.y);
    v.z = rna_tf32(v.z); v.w = rna_tf32(v.w);
    *(float4*)(out + i) = v;
}

// ---------------------------------------------------------------------------
// Weight transpose + round-to-nearest tf32: out[n*R + r] = rna(in[r*C + n])
// ---------------------------------------------------------------------------
__global__ __launch_bounds__(256)
void transpose_rnd(const float* __restrict__ in, float* __restrict__ out,
                   int R, int C)
{
    __shared__ float t[32][33];
    const int c0 = blockIdx.x * 32, r0 = blockIdx.y * 32;
    const int x = threadIdx.x, y = threadIdx.y;
#pragma unroll
    for (int i = 0; i < 32; i += 8)
        t[y + i][x] = in[(size_t)(r0 + y + i) * C + c0 + x];
    __syncthreads();
#pragma unroll
    for (int i = 0; i < 32; i += 8)
        out[(size_t)(c0 + y + i) * R + r0 + x] = rna_tf32(t[x][y + i]);
}

// ---------------------------------------------------------------------------
// Row LayerNorm + ReLU in place, output rounded to tf32 (rna).
// ---------------------------------------------------------------------------
__global__ __launch_bounds__(256)
void ln_relu(float* __restrict__ H, const float* __restrict__ g,
             const float* __restrict__ be)
{
    const int row = blockIdx.x;
    const int tid = threadIdx.x;
    float4* p = (float4*)(H + (size_t)row * 1024);

    float4 v = p[tid];
    float s  = v.x + v.y + v.z + v.w;
    float sq = v.x * v.x + v.y * v.y + v.z * v.z + v.w * v.w;

    __shared__ float ss[8], ssq[8];
    const int lane = tid & 31, warp = tid >> 5;
#pragma unroll
    for (int o = 16; o > 0; o >>= 1) {
        s  += __shfl_down_sync(0xffffffffu, s,  o);
        sq += __shfl_down_sync(0xffffffffu, sq, o);
    }
    if (lane == 0) { ss[warp] = s; ssq[warp] = sq; }
    __syncthreads();
    if (warp == 0) {
        s  = (lane < 8) ? ss[lane]  : 0.f;
        sq = (lane < 8) ? ssq[lane] : 0.f;
#pragma unroll
        for (int o = 4; o > 0; o >>= 1) {
            s  += __shfl_down_sync(0xffffffffu, s,  o);
            sq += __shfl_down_sync(0xffffffffu, sq, o);
        }
        if (lane == 0) { ss[0] = s; ssq[0] = sq; }
    }
    __syncthreads();

    const float mean = ss[0] * (1.0f / 1024.0f);
    const float var  = ssq[0] * (1.0f / 1024.0f) - mean * mean;
    const float rstd = rsqrtf(var + 1e-6f);

    float4 gv = ((const float4*)g)[tid];
    float4 bv = ((const float4*)be)[tid];
    float4 o;
    o.x = rna_tf32(fmaxf(fmaf((v.x - mean) * rstd, gv.x, bv.x), 0.f));
    o.y = rna_tf32(fmaxf(fmaf((v.y - mean) * rstd, gv.y, bv.y), 0.f));
    o.z = rna_tf32(fmaxf(fmaf((v.z - mean) * rstd, gv.z, bv.z), 0.f));
    o.w = rna_tf32(fmaxf(fmaf((v.w - mean) * rstd, gv.w, bv.w), 0.f));
    p[tid] = o;
}

// ---------------------------------------------------------------------------
// Output layer: out[row] = relu(dot(H[row,:], Wout) + bout). Warp per row.
// ---------------------------------------------------------------------------
__global__ __launch_bounds__(256)
void out_layer(const float* __restrict__ H, const float* __restrict__ Wout,
               const float* __restrict__ bout, float* __restrict__ out)
{
    const int row  = blockIdx.x * 8 + (threadIdx.x >> 5);
    const int lane = threadIdx.x & 31;
    const float* p = H + (size_t)row * 1024;

    float s = 0.f;
#pragma unroll
    for (int t = 0; t < 32; t++) {
        const int j = t * 32 + lane;
        s = fmaf(p[j], __ldg(Wout + j), s);
    }
#pragma unroll
    for (int o = 16; o > 0; o >>= 1) s += __shfl_down_sync(0xffffffffu, s, o);
    if (lane == 0) out[row] = fmaxf(s + bout[0], 0.f);
}

// ---------------------------------------------------------------------------
extern "C" void kernel_launch(void* const* d_in, const int* in_sizes, int n_in,
                              void* d_out, int out_size)
{
    const float* X    = (const float*)d_in[0];
    const float* W0   = (const float*)d_in[1];
    const float* b0   = (const float*)d_in[2];
    const float* W1   = (const float*)d_in[3];
    const float* g1   = (const float*)d_in[4];
    const float* be1  = (const float*)d_in[5];
    const float* W2   = (const float*)d_in[6];
    const float* g2   = (const float*)d_in[7];
    const float* be2  = (const float*)d_in[8];
    const float* W3   = (const float*)d_in[9];
    const float* g3   = (const float*)d_in[10];
    const float* be3  = (const float*)d_in[11];
    const float* Wout = (const float*)d_in[12];
    const float* bout = (const float*)d_in[13];
    float* out = (float*)d_out;

    float *bufA, *bufB, *wt0, *wt1, *wt2, *wt3;
    cudaGetSymbolAddress((void**)&bufA, g_bufA);
    cudaGetSymbolAddress((void**)&bufB, g_bufB);
    cudaGetSymbolAddress((void**)&wt0, g_wt0);
    cudaGetSymbolAddress((void**)&wt1, g_wt1);
    cudaGetSymbolAddress((void**)&wt2, g_wt2);
    cudaGetSymbolAddress((void**)&wt3, g_wt3);

    constexpr int SMEM_REQ = 3 * 32768;   // 96 KB
    cudaFuncSetAttribute(gemm_mma<D_IN, 1>,
                         cudaFuncAttributeMaxDynamicSharedMemorySize, SMEM_REQ);
    cudaFuncSetAttribute(gemm_mma<HID, 0>,
                         cudaFuncAttributeMaxDynamicSharedMemorySize, SMEM_REQ);

    // tf32-round X into bufB; transpose+round weights
    round_copy<<<(N_ROWS * D_IN) / (256 * 4), 256>>>(X, bufB);
    transpose_rnd<<<dim3(HID / 32, D_IN / 32), dim3(32, 8)>>>(W0, wt0, D_IN, HID);
    transpose_rnd<<<dim3(HID / 32, HID / 32), dim3(32, 8)>>>(W1, wt1, HID, HID);
    transpose_rnd<<<dim3(HID / 32, HID / 32), dim3(32, 8)>>>(W2, wt2, HID, HID);
    transpose_rnd<<<dim3(HID / 32, HID / 32), dim3(32, 8)>>>(W3, wt3, HID, HID);

    const dim3 grid(HID / 128, N_ROWS / 128);   // (8, 512)

    // layer 0: Dense + bias + relu (+tf32 round for next layer's A)
    gemm_mma<D_IN, 1><<<grid, 256, SMEM_REQ>>>(bufB, wt0, b0, bufA);

    // hidden layers: Dense -> LN(+relu, round)
    gemm_mma<HID, 0><<<grid, 256, SMEM_REQ>>>(bufA, wt1, nullptr, bufB);
    ln_relu<<<N_ROWS, 256>>>(bufB, g1, be1);

    gemm_mma<HID, 0><<<grid, 256, SMEM_REQ>>>(bufB, wt2, nullptr, bufA);
    ln_relu<<<N_ROWS, 256>>>(bufA, g2, be2);

    gemm_mma<HID, 0><<<grid, 256, SMEM_REQ>>>(bufA, wt3, nullptr, bufB);
    ln_relu<<<N_ROWS, 256>>>(bufB, g3, be3);

    // output layer
    out_layer<<<N_ROWS / 8, 256>>>(bufB, Wout, bout, out);
}

// round 4
// speedup vs baseline: 6.5123x; 1.6238x over previous
#include <cuda_runtime.h>
#include <cuda_fp16.h>
#include <cstdint>
#include <cstddef>

#define N_ROWS 65536
#define HID    1024
#define D_IN   512

// ---------------- scratch (__device__ globals: the sanctioned mechanism) ----
__device__ __align__(128) __half g_hX[(size_t)N_ROWS * D_IN];
__device__ __align__(128) __half g_hA[(size_t)N_ROWS * HID];
__device__ __align__(128) __half g_hB[(size_t)N_ROWS * HID];
__device__ __align__(128) float  g_bufF[(size_t)N_ROWS * HID];
__device__ __align__(128) __half g_wh0[HID * D_IN];   // W0^T [1024][512]
__device__ __align__(128) __half g_wh1[HID * HID];
__device__ __align__(128) __half g_wh2[HID * HID];
__device__ __align__(128) __half g_wh3[HID * HID];

// ---------------- helpers ---------------------------------------------------
__device__ __forceinline__ uint32_t smem_u32(const void* p) {
    uint32_t a;
    asm("{ .reg .u64 t; cvta.to.shared.u64 t, %1; cvt.u32.u64 %0, t; }"
        : "=r"(a) : "l"(p));
    return a;
}
__device__ __forceinline__ void ldsm_x4(uint32_t* d, uint32_t addr) {
    asm volatile("ldmatrix.sync.aligned.m8n8.x4.shared.b16 {%0,%1,%2,%3}, [%4];"
                 : "=r"(d[0]), "=r"(d[1]), "=r"(d[2]), "=r"(d[3]) : "r"(addr));
}
__device__ __forceinline__ void mma_f16(float* c, const uint32_t* a,
                                        uint32_t b0, uint32_t b1) {
    asm volatile(
        "mma.sync.aligned.m16n8k16.row.col.f32.f16.f16.f32 "
        "{%0,%1,%2,%3}, {%4,%5,%6,%7}, {%8,%9}, {%0,%1,%2,%3};"
        : "+f"(c[0]), "+f"(c[1]), "+f"(c[2]), "+f"(c[3])
        : "r"(a[0]), "r"(a[1]), "r"(a[2]), "r"(a[3]), "r"(b0), "r"(b1));
}
__device__ __forceinline__ void cp16(uint32_t dst, const void* src) {
    asm volatile("cp.async.cg.shared.global [%0], [%1], 16;" :: "r"(dst), "l"(src));
}

// ---------------------------------------------------------------------------
// fp16 mma.sync GEMM: C[M,1024] = A[M,K] @ Bt[1024,K]^T  (fp32 accum)
// BM=128, BN=128, BK=32, 4-stage cp.async pipeline, 256 threads (8 warps),
// warp tile 64x32 (m16n8k16). Rows = 32 halves = 64B; 16B-chunk XOR swizzle:
// phys_chunk = chunk ^ ((row>>1)&3)  -> conflict-free cp.async + ldmatrix.
// EPI=1: half out = rn(relu(acc+bias)); EPI=0: raw fp32 out.
// ---------------------------------------------------------------------------
template<int K, int EPI>
__global__ __launch_bounds__(256, 2)
void gemm_h(const __half* __restrict__ A, const __half* __restrict__ Bt,
            const float* __restrict__ bias, void* __restrict__ Cout)
{
    constexpr int KT = K / 32;
    constexpr int STAGE = 16384;               // A 8K + B 8K

    extern __shared__ char smem[];
    const uint32_t sb = smem_u32(smem);

    const int tid  = threadIdx.x;
    const int lane = tid & 31, warp = tid >> 5;
    const int wm   = warp & 1;                  // 2 warps in m
    const int wn   = warp >> 1;                 // 4 warps in n
    const int m0   = blockIdx.y * 128;
    const int n0   = blockIdx.x * 128;

    // ---- cp.async geometry: 512 chunks (16B) per matrix, 2 per thread ----
    const int ldr = tid >> 2;                   // 0..63
    const int ldc = tid & 3;                    // chunk 0..3
    const __half* Ag = A  + (size_t)(m0 + ldr) * K + ldc * 8;
    const __half* Bg = Bt + (size_t)(n0 + ldr) * K + ldc * 8;

    auto load_tile = [&](int kt) {
        const uint32_t st = sb + (uint32_t)(kt & 3) * STAGE;
        const __half* ag = Ag + kt * 32;
        const __half* bg = Bg + kt * 32;
#pragma unroll
        for (int i = 0; i < 2; i++) {
            const int r = ldr + i * 64;
            const uint32_t off = (uint32_t)(r * 64 + ((ldc ^ ((r >> 1) & 3)) * 16));
            cp16(st + off,        ag + (size_t)i * 64 * K);
            cp16(st + 8192 + off, bg + (size_t)i * 64 * K);
        }
        asm volatile("cp.async.commit_group;" ::: "memory");
    };

    // ---- ldmatrix per-thread geometry ----
    const uint32_t ArowL = (uint32_t)(wm * 64 + (lane & 15));
    const uint32_t hiA   = (uint32_t)(lane >> 4);              // +kchunk
    const uint32_t BrowL = (uint32_t)(wn * 32 + (lane & 7) + ((lane >> 4) << 3));
    const uint32_t hiB   = (uint32_t)((lane >> 3) & 1);        // +kchunk

    float acc[4][4][4];
#pragma unroll
    for (int i = 0; i < 4; i++)
#pragma unroll
        for (int j = 0; j < 4; j++)
#pragma unroll
            for (int q = 0; q < 4; q++) acc[i][j][q] = 0.f;

    load_tile(0); load_tile(1); load_tile(2);

    for (int kt = 0; kt < KT; kt++) {
        if (kt + 3 <= KT)      asm volatile("cp.async.wait_group 2;" ::: "memory");
        else if (kt + 2 == KT) asm volatile("cp.async.wait_group 1;" ::: "memory");
        else                   asm volatile("cp.async.wait_group 0;" ::: "memory");
        __syncthreads();
        if (kt + 3 < KT) load_tile(kt + 3);

        const uint32_t stA = sb + (uint32_t)(kt & 3) * STAGE;
        const uint32_t stB = stA + 8192;

#pragma unroll
        for (int ks = 0; ks < 2; ks++) {
            uint32_t a[4][4];
#pragma unroll
            for (int mi = 0; mi < 4; mi++) {
                const uint32_t r = ArowL + mi * 16;
                const uint32_t kc = (uint32_t)(ks * 2) + hiA;
                ldsm_x4(a[mi], stA + r * 64 + ((kc ^ ((r >> 1) & 3)) * 16));
            }
            uint32_t b[2][4];
#pragma unroll
            for (int np = 0; np < 2; np++) {
                const uint32_t r = BrowL + np * 16;
                const uint32_t kc = (uint32_t)(ks * 2) + hiB;
                ldsm_x4(b[np], stB + r * 64 + ((kc ^ ((r >> 1) & 3)) * 16));
            }
#pragma unroll
            for (int mi = 0; mi < 4; mi++)
#pragma unroll
                for (int ni = 0; ni < 4; ni++)
                    mma_f16(acc[mi][ni], a[mi],
                            b[ni >> 1][(ni & 1) * 2], b[ni >> 1][(ni & 1) * 2 + 1]);
        }
    }

    // ---- epilogue ----
#pragma unroll
    for (int mi = 0; mi < 4; mi++) {
        const int r = m0 + wm * 64 + mi * 16 + (lane >> 2);
#pragma unroll
        for (int ni = 0; ni < 4; ni++) {
            const int col = n0 + wn * 32 + ni * 8 + (lane & 3) * 2;
            float c0 = acc[mi][ni][0], c1 = acc[mi][ni][1];
            float c2 = acc[mi][ni][2], c3 = acc[mi][ni][3];
            if (EPI) {
                __half* C = (__half*)Cout;
                const float b0v = bias[col], b1v = bias[col + 1];
                __half2 h0 = __floats2half2_rn(fmaxf(c0 + b0v, 0.f),
                                               fmaxf(c1 + b1v, 0.f));
                __half2 h1 = __floats2half2_rn(fmaxf(c2 + b0v, 0.f),
                                               fmaxf(c3 + b1v, 0.f));
                *(__half2*)(C + (size_t)r * HID + col)       = h0;
                *(__half2*)(C + (size_t)(r + 8) * HID + col) = h1;
            } else {
                float* C = (float*)Cout;
                *(float2*)(C + (size_t)r * HID + col)       = make_float2(c0, c1);
                *(float2*)(C + (size_t)(r + 8) * HID + col) = make_float2(c2, c3);
            }
        }
    }
}

// ---------------------------------------------------------------------------
// Round-copy fp32 -> fp16 (rn): for raw input X.
// ---------------------------------------------------------------------------
__global__ __launch_bounds__(256)
void round_copy_h(const float* __restrict__ in, __half* __restrict__ out)
{
    const size_t i = ((size_t)blockIdx.x * 256 + threadIdx.x) * 4;
    float4 v = *(const float4*)(in + i);
    __half2 h0 = __floats2half2_rn(v.x, v.y);
    __half2 h1 = __floats2half2_rn(v.z, v.w);
    *(__half2*)(out + i)     = h0;
    *(__half2*)(out + i + 2) = h1;
}

// ---------------------------------------------------------------------------
// Weight transpose + fp16 round: out[n*R + r] = half_rn(in[r*C + n])
// ---------------------------------------------------------------------------
__global__ __launch_bounds__(256)
void transpose_h(const float* __restrict__ in, __half* __restrict__ out,
                 int R, int C)
{
    __shared__ float t[32][33];
    const int c0 = blockIdx.x * 32, r0 = blockIdx.y * 32;
    const int x = threadIdx.x, y = threadIdx.y;
#pragma unroll
    for (int i = 0; i < 32; i += 8)
        t[y + i][x] = in[(size_t)(r0 + y + i) * C + c0 + x];
    __syncthreads();
#pragma unroll
    for (int i = 0; i < 32; i += 8)
        out[(size_t)(c0 + y + i) * R + r0 + x] = __float2half_rn(t[x][y + i]);
}

// ---------------------------------------------------------------------------
// LayerNorm (fp32 in) + ReLU -> fp16 out. One block (256 thr) per row of 1024.
// ---------------------------------------------------------------------------
__global__ __launch_bounds__(256)
void ln_relu_h(const float* __restrict__ H, const float* __restrict__ g,
               const float* __restrict__ be, __half* __restrict__ O)
{
    const int row = blockIdx.x;
    const int tid = threadIdx.x;
    const float4 v = ((const float4*)(H + (size_t)row * 1024))[tid];
    float s  = v.x + v.y + v.z + v.w;
    float sq = v.x * v.x + v.y * v.y + v.z * v.z + v.w * v.w;

    __shared__ float ss[8], ssq[8];
    const int lane = tid & 31, warp = tid >> 5;
#pragma unroll
    for (int o = 16; o > 0; o >>= 1) {
        s  += __shfl_down_sync(0xffffffffu, s,  o);
        sq += __shfl_down_sync(0xffffffffu, sq, o);
    }
    if (lane == 0) { ss[warp] = s; ssq[warp] = sq; }
    __syncthreads();
    if (warp == 0) {
        s  = (lane < 8) ? ss[lane]  : 0.f;
        sq = (lane < 8) ? ssq[lane] : 0.f;
#pragma unroll
        for (int o = 4; o > 0; o >>= 1) {
            s  += __shfl_down_sync(0xffffffffu, s,  o);
            sq += __shfl_down_sync(0xffffffffu, sq, o);
        }
        if (lane == 0) { ss[0] = s; ssq[0] = sq; }
    }
    __syncthreads();

    const float mean = ss[0] * (1.0f / 1024.0f);
    const float var  = ssq[0] * (1.0f / 1024.0f) - mean * mean;
    const float rstd = rsqrtf(var + 1e-6f);

    const float4 gv = ((const float4*)g)[tid];
    const float4 bv = ((const float4*)be)[tid];
    const float ox = fmaxf(fmaf((v.x - mean) * rstd, gv.x, bv.x), 0.f);
    const float oy = fmaxf(fmaf((v.y - mean) * rstd, gv.y, bv.y), 0.f);
    const float oz = fmaxf(fmaf((v.z - mean) * rstd, gv.z, bv.z), 0.f);
    const float ow = fmaxf(fmaf((v.w - mean) * rstd, gv.w, bv.w), 0.f);

    __half* op = O + (size_t)row * 1024 + tid * 4;
    *(__half2*)(op)     = __floats2half2_rn(ox, oy);
    *(__half2*)(op + 2) = __floats2half2_rn(oz, ow);
}

// ---------------------------------------------------------------------------
// Final fused: LayerNorm + ReLU + dot(Wout) + bias + ReLU -> out[row].
// Keeps layer-3 activations in fp32 (no rounding) for extra accuracy.
// ---------------------------------------------------------------------------
__global__ __launch_bounds__(256)
void ln_dot(const float* __restrict__ H, const float* __restrict__ g,
            const float* __restrict__ be, const float* __restrict__ Wout,
            const float* __restrict__ bout, float* __restrict__ out)
{
    const int row = blockIdx.x;
    const int tid = threadIdx.x;
    const float4 v = ((const float4*)(H + (size_t)row * 1024))[tid];
    float s  = v.x + v.y + v.z + v.w;
    float sq = v.x * v.x + v.y * v.y + v.z * v.z + v.w * v.w;

    __shared__ float ss[8], ssq[8];
    const int lane = tid & 31, warp = tid >> 5;
#pragma unroll
    for (int o = 16; o > 0; o >>= 1) {
        s  += __shfl_down_sync(0xffffffffu, s,  o);
        sq += __shfl_down_sync(0xffffffffu, sq, o);
    }
    if (lane == 0) { ss[warp] = s; ssq[warp] = sq; }
    __syncthreads();
    if (warp == 0) {
        s  = (lane < 8) ? ss[lane]  : 0.f;
        sq = (lane < 8) ? ssq[lane] : 0.f;
#pragma unroll
        for (int o = 4; o > 0; o >>= 1) {
            s  += __shfl_down_sync(0xffffffffu, s,  o);
            sq += __shfl_down_sync(0xffffffffu, sq, o);
        }
        if (lane == 0) { ss[0] = s; ssq[0] = sq; }
    }
    __syncthreads();

    const float mean = ss[0] * (1.0f / 1024.0f);
    const float var  = ssq[0] * (1.0f / 1024.0f) - mean * mean;
    const float rstd = rsqrtf(var + 1e-6f);

    const float4 gv = ((const float4*)g)[tid];
    const float4 bv = ((const float4*)be)[tid];
    const float4 wv = ((const float4*)Wout)[tid];
    float d = 0.f;
    d = fmaf(fmaxf(fmaf((v.x - mean) * rstd, gv.x, bv.x), 0.f), wv.x, d);
    d = fmaf(fmaxf(fmaf((v.y - mean) * rstd, gv.y, bv.y), 0.f), wv.y, d);
    d = fmaf(fmaxf(fmaf((v.z - mean) * rstd, gv.z, bv.z), 0.f), wv.z, d);
    d = fmaf(fmaxf(fmaf((v.w - mean) * rstd, gv.w, bv.w), 0.f), wv.w, d);

#pragma unroll
    for (int o = 16; o > 0; o >>= 1) d += __shfl_down_sync(0xffffffffu, d, o);
    if (lane == 0) ss[warp] = d;
    __syncthreads();
    if (tid == 0) {
        float t = 0.f;
#pragma unroll
        for (int w = 0; w < 8; w++) t += ss[w];
        out[row] = fmaxf(t + bout[0], 0.f);
    }
}

// ---------------------------------------------------------------------------
extern "C" void kernel_launch(void* const* d_in, const int* in_sizes, int n_in,
                              void* d_out, int out_size)
{
    const float* X    = (const float*)d_in[0];
    const float* W0   = (const float*)d_in[1];
    const float* b0   = (const float*)d_in[2];
    const float* W1   = (const float*)d_in[3];
    const float* g1   = (const float*)d_in[4];
    const float* be1  = (const float*)d_in[5];
    const float* W2   = (const float*)d_in[6];
    const float* g2   = (const float*)d_in[7];
    const float* be2  = (const float*)d_in[8];
    const float* W3   = (const float*)d_in[9];
    const float* g3   = (const float*)d_in[10];
    const float* be3  = (const float*)d_in[11];
    const float* Wout = (const float*)d_in[12];
    const float* bout = (const float*)d_in[13];
    float* out = (float*)d_out;

    __half *hX, *hA, *hB, *wh0, *wh1, *wh2, *wh3;
    float* bufF;
    cudaGetSymbolAddress((void**)&hX,  g_hX);
    cudaGetSymbolAddress((void**)&hA,  g_hA);
    cudaGetSymbolAddress((void**)&hB,  g_hB);
    cudaGetSymbolAddress((void**)&bufF, g_bufF);
    cudaGetSymbolAddress((void**)&wh0, g_wh0);
    cudaGetSymbolAddress((void**)&wh1, g_wh1);
    cudaGetSymbolAddress((void**)&wh2, g_wh2);
    cudaGetSymbolAddress((void**)&wh3, g_wh3);

    constexpr int SMEM_REQ = 4 * 16384;   // 64 KB
    cudaFuncSetAttribute(gemm_h<D_IN, 1>,
                         cudaFuncAttributeMaxDynamicSharedMemorySize, SMEM_REQ);
    cudaFuncSetAttribute(gemm_h<HID, 0>,
                         cudaFuncAttributeMaxDynamicSharedMemorySize, SMEM_REQ);

    // prep: round X to fp16; transpose + round weights
    round_copy_h<<<(N_ROWS * D_IN) / (256 * 4), 256>>>(X, hX);
    transpose_h<<<dim3(HID / 32, D_IN / 32), dim3(32, 8)>>>(W0, wh0, D_IN, HID);
    transpose_h<<<dim3(HID / 32, HID / 32), dim3(32, 8)>>>(W1, wh1, HID, HID);
    transpose_h<<<dim3(HID / 32, HID / 32), dim3(32, 8)>>>(W2, wh2, HID, HID);
    transpose_h<<<dim3(HID / 32, HID / 32), dim3(32, 8)>>>(W3, wh3, HID, HID);

    const dim3 grid(HID / 128, N_ROWS / 128);   // (8, 512)

    // layer 0: Dense + bias + relu -> half
    gemm_h<D_IN, 1><<<grid, 256, SMEM_REQ>>>(hX, wh0, b0, hA);

    // hidden layers: Dense (fp32 out) -> LN+relu (-> half)
    gemm_h<HID, 0><<<grid, 256, SMEM_REQ>>>(hA, wh1, nullptr, bufF);
    ln_relu_h<<<N_ROWS, 256>>>(bufF, g1, be1, hB);

    gemm_h<HID, 0><<<grid, 256, SMEM_REQ>>>(hB, wh2, nullptr, bufF);
    ln_relu_h<<<N_ROWS, 256>>>(bufF, g2, be2, hA);

    gemm_h<HID, 0><<<grid, 256, SMEM_REQ>>>(hA, wh3, nullptr, bufF);

    // final: LN + relu + Dense(1) + relu, fused
    ln_dot<<<N_ROWS, 256>>>(bufF, g3, be3, Wout, bout, out);
}